// round 12
// baseline (speedup 1.0000x reference)
#include <cuda_runtime.h>

// Fused maxpool-argmax + sigma gather. Scattered-direct design (best measured
// bandwidth across R5-R11), tuned for request supply:
//   - 4 output columns per thread -> STG.128 stores, 4 independent gather
//     loads per row per thread, unroll 2 rows = 8 loads in flight.
//   - __launch_bounds__(256, 8): 8 CTAs/SM, 1024 blocks ~ one wave.
//   - No sigma staging in smem (proven useless R9/R11), only scol (1KB).
//
// Grid: 128 bc * 8 chunks = 1024 blocks, 256 threads.
// Thread t: column group 4*(t&63), row-phase t>>6; rows i0+phase+4r, r=0..7.
__global__ __launch_bounds__(256, 8)
void fused_pool_gather_kernel(const float* __restrict__ mu,
                              const float* __restrict__ sigma,
                              float* __restrict__ out_mu,
                              float* __restrict__ out_sig) {
    __shared__ int scol[256];

    const int bc    = blockIdx.x >> 3;    // 0..127
    const int chunk = blockIdx.x & 7;     // 0..7 (32 output rows)
    const int tid   = threadIdx.x;

    // ---- pool/argmax for window `tid` (mu: 4KB/bc, L2-resident) ----
    {
        const int ho = tid >> 4;
        const int wo = tid & 15;
        const float* base = mu + (size_t)bc * 1024;
        const int r0 = 2 * ho;
        const int c0 = 2 * wo;

        const float v0 = base[r0 * 32 + c0];
        const float v1 = base[r0 * 32 + c0 + 1];
        const float v2 = base[(r0 + 1) * 32 + c0];
        const float v3 = base[(r0 + 1) * 32 + c0 + 1];

        float m = v0; int k = 0;
        if (v1 > m) { m = v1; k = 1; }    // strict >: first-max (jnp.argmax)
        if (v2 > m) { m = v2; k = 2; }
        if (v3 > m) { m = v3; k = 3; }

        scol[tid] = (r0 + (k >> 1)) * 32 + (c0 + (k & 1));
        if (chunk == 0) out_mu[bc * 256 + tid] = m;
    }
    __syncthreads();

    // ---- gather: thread owns 4 adjacent output columns ----
    const int cg = (tid & 63) << 2;       // column group start: 0,4,...,252
    const int rq = tid >> 6;              // row phase 0..3

    const int c0 = scol[cg];              // this thread's 4 picked columns
    const int c1 = scol[cg + 1];
    const int c2 = scol[cg + 2];
    const int c3 = scol[cg + 3];

    const float* sb = sigma   + ((size_t)bc << 20);
    float*       ob = out_sig + (size_t)bc * 65536;
    const int    i0 = chunk * 32 + rq;    // rows: i0 + 4*r, r=0..7

    #pragma unroll
    for (int r = 0; r < 8; r += 2) {
        const int iA = i0 + 4 * r;
        const int iB = iA + 4;
        const size_t rA = (size_t)scol[iA] << 10;   // broadcast LDS
        const size_t rB = (size_t)scol[iB] << 10;

        float4 a, b;                       // 8 independent scattered loads
        a.x = __ldcs(sb + rA + c0);
        a.y = __ldcs(sb + rA + c1);
        a.z = __ldcs(sb + rA + c2);
        a.w = __ldcs(sb + rA + c3);
        b.x = __ldcs(sb + rB + c0);
        b.y = __ldcs(sb + rB + c1);
        b.z = __ldcs(sb + rB + c2);
        b.w = __ldcs(sb + rB + c3);

        *(float4*)(ob + (size_t)iA * 256 + cg) = a;   // STG.128, coalesced
        *(float4*)(ob + (size_t)iB * 256 + cg) = b;
    }
}

extern "C" void kernel_launch(void* const* d_in, const int* in_sizes, int n_in,
                              void* d_out, int out_size) {
    const float* mu    = (const float*)d_in[0];
    const float* sigma = (const float*)d_in[1];
    if (n_in >= 2 && in_sizes[0] > in_sizes[1]) {
        sigma = (const float*)d_in[0];
        mu    = (const float*)d_in[1];
    }

    float* out_mu  = (float*)d_out;            // 32768 elements
    float* out_sig = out_mu + 32768;           // 8388608 elements

    fused_pool_gather_kernel<<<1024, 256>>>(mu, sigma, out_mu, out_sig);
}

// round 13
// speedup vs baseline: 1.0468x; 1.0468x over previous
#include <cuda_runtime.h>

// Fused maxpool-argmax + sigma gather.
// Winning access pattern (R6): thread j <-> output column j, so each warp-LDG's
// 32 picks fall in a 128-float flat range (<=4 lines). R12 proved wider spans
// cost 4x L1tex wavefronts. Delta vs R6: explicit 8-deep register batching
// (8 independent LDGs in flight before dependent stores), streaming stores,
// and 2048 blocks so a wave packs 8 CTAs/SM.
//
// Grid: 128 bc * 16 chunks = 2048 blocks, 256 threads.
__global__ __launch_bounds__(256, 8)
void fused_pool_gather_kernel(const float* __restrict__ mu,
                              const float* __restrict__ sigma,
                              float* __restrict__ out_mu,
                              float* __restrict__ out_sig) {
    __shared__ int scol[256];

    const int bc    = blockIdx.x >> 4;    // 0..127
    const int chunk = blockIdx.x & 15;    // 0..15 (16 output rows each)
    const int tid   = threadIdx.x;        // output column j

    // ---- pool/argmax for window `tid` (mu: 4KB/bc, L2-resident) ----
    {
        const int ho = tid >> 4;
        const int wo = tid & 15;
        const float* base = mu + (size_t)bc * 1024;
        const int r0 = 2 * ho;
        const int c0 = 2 * wo;

        const float v0 = base[r0 * 32 + c0];
        const float v1 = base[r0 * 32 + c0 + 1];
        const float v2 = base[(r0 + 1) * 32 + c0];
        const float v3 = base[(r0 + 1) * 32 + c0 + 1];

        float m = v0; int k = 0;
        if (v1 > m) { m = v1; k = 1; }    // strict >: first-max (jnp.argmax)
        if (v2 > m) { m = v2; k = 2; }
        if (v3 > m) { m = v3; k = 3; }

        scol[tid] = (r0 + (k >> 1)) * 32 + (c0 + (k & 1));
        if (chunk == 0) out_mu[bc * 256 + tid] = m;
    }
    __syncthreads();

    // ---- gather: out[i][tid] = sigma[bc][scol[i]][scol[tid]] ----
    const int    cj = scol[tid];
    const float* sb = sigma   + ((size_t)bc << 20);
    float*       ob = out_sig + (size_t)bc * 65536 + tid;
    const int    i0 = chunk * 16;

    #pragma unroll
    for (int b = 0; b < 2; ++b) {
        const int ibase = i0 + b * 8;
        float v[8];
        // 8 independent scattered LDGs back-to-back (rows broadcast via LDS).
        #pragma unroll
        for (int t = 0; t < 8; ++t)
            v[t] = __ldcs(sb + ((size_t)scol[ibase + t] << 10) + cj);
        // 8 coalesced streaming stores (full 128B lines per warp).
        #pragma unroll
        for (int t = 0; t < 8; ++t)
            __stcs(ob + (size_t)(ibase + t) * 256, v[t]);
    }
}

extern "C" void kernel_launch(void* const* d_in, const int* in_sizes, int n_in,
                              void* d_out, int out_size) {
    const float* mu    = (const float*)d_in[0];
    const float* sigma = (const float*)d_in[1];
    if (n_in >= 2 && in_sizes[0] > in_sizes[1]) {
        sigma = (const float*)d_in[0];
        mu    = (const float*)d_in[1];
    }

    float* out_mu  = (float*)d_out;            // 32768 elements
    float* out_sig = out_mu + 32768;           // 8388608 elements

    fused_pool_gather_kernel<<<2048, 256>>>(mu, sigma, out_mu, out_sig);
}